// round 15
// baseline (speedup 1.0000x reference)
#include <cuda_runtime.h>

// Problem constants
#define NB 4
#define NN 8192
#define MCHUNK 512             // m's per chunk (SMEM tile)
#define NCH (NN / MCHUNK)      // 16 m-chunks
#define THREADS 128
#define QPT 4                  // queries per thread (as 2 packed query-pairs)
#define QBLK (THREADS * QPT)   // 512 queries per CTA
#define NQB (NN / QBLK)        // 16 query blocks

// Per-(batch, m-chunk, query) partials: {sum_e, ax, ay, az}. 4*16*8192*16B = 8MB (L2-resident).
__device__ float4 g_partial[NB * NCH * NN];

// ---------- f32x2 helpers (sm_103a packed fp32) ----------
__device__ __forceinline__ unsigned long long pack2(float lo, float hi) {
    unsigned long long r;
    asm("mov.b64 %0, {%1, %2};" : "=l"(r) : "f"(lo), "f"(hi));
    return r;
}
__device__ __forceinline__ void unpack2(unsigned long long v, float& lo, float& hi) {
    asm("mov.b64 {%0, %1}, %2;" : "=f"(lo), "=f"(hi) : "l"(v));
}
__device__ __forceinline__ unsigned long long fma2(unsigned long long a, unsigned long long b,
                                                   unsigned long long c) {
    unsigned long long r;
    asm("fma.rn.f32x2 %0, %1, %2, %3;" : "=l"(r) : "l"(a), "l"(b), "l"(c));
    return r;
}
__device__ __forceinline__ unsigned long long mul2(unsigned long long a, unsigned long long b) {
    unsigned long long r;
    asm("mul.rn.f32x2 %0, %1, %2;" : "=l"(r) : "l"(a), "l"(b));
    return r;
}
__device__ __forceinline__ unsigned long long add2(unsigned long long a, unsigned long long b) {
    unsigned long long r;
    asm("add.rn.f32x2 %0, %1, %2;" : "=l"(r) : "l"(a), "l"(b));
    return r;
}
// ex2 on both halves of a packed f32x2 (ptxas coalesces the movs when
// register allocation permits).
__device__ __forceinline__ unsigned long long ex2_pair(unsigned long long s2) {
    unsigned long long r;
    asm("{\n\t"
        ".reg .f32 lo, hi;\n\t"
        "mov.b64 {lo, hi}, %1;\n\t"
        "ex2.approx.ftz.f32 lo, lo;\n\t"
        "ex2.approx.ftz.f32 hi, hi;\n\t"
        "mov.b64 %0, {lo, hi};\n\t"
        "}" : "=l"(r) : "l"(s2));
    return r;
}

// log2(e) / sqrt(3): folds the attention scale and the exp->ex2 conversion into q.
#define QFOLD 0.8329433338549414f

// ---------------------------------------------------------------------------
// Kernel 1: per (batch, m-chunk) partial softmax numerators.
// Packing axis = QUERY pairs: smem holds k/v components pre-duplicated
// ({kx,kx},{ky,ky},...), each thread carries 2 packed query-pairs
// ({q_a,q_b} per component). This halves q-pack + accumulator registers
// (~96 -> ~70) so 6 CTAs (24 warps) fit per SM for latency absorption.
// Warp smem reads are same-address broadcasts (conflict-free).
// ---------------------------------------------------------------------------
__global__ __launch_bounds__(THREADS, 6) void attn_partial_kernel(
    const float* __restrict__ X,   // (B, N, 3)
    const float* __restrict__ W,   // (9, 3) row-major
    const float* __restrict__ Bq)  // (9,)
{
    // Per m: 12 floats [kx kx ky ky | kz kz vx vx | vy vy vz vz] = 48B,
    // 16B-aligned triplets -> 3 x LDS.128, each half a ready f32x2 operand.
    __shared__ __align__(16) float skv[MCHUNK * 12];   // 24 KB

    const int ch  = blockIdx.x;   // m-chunk
    const int qb  = blockIdx.y;   // query block
    const int b   = blockIdx.z;   // batch
    const int tid = threadIdx.x;

    const float* xb = X + (size_t)b * NN * 3;

    // ---- Fill SMEM: project k,v for this m-chunk (4 m's per thread) ----
    #pragma unroll
    for (int i = 0; i < MCHUNK; i += THREADS) {
        const int ml = i + tid;
        const int m  = ch * MCHUNK + ml;
        const float x0 = xb[m * 3 + 0];
        const float x1 = xb[m * 3 + 1];
        const float x2 = xb[m * 3 + 2];
        float2* base = reinterpret_cast<float2*>(skv + 12 * ml);
        #pragma unroll
        for (int j = 0; j < 3; j++) {
            // k_j = qkv column 3j+1, v_j = column 3j+2
            const int ck = (3 * j + 1) * 3;
            const int cv = (3 * j + 2) * 3;
            float kj = W[ck + 0] * x0 + W[ck + 1] * x1 + W[ck + 2] * x2 + Bq[3 * j + 1];
            float vj = W[cv + 0] * x0 + W[cv + 1] * x1 + W[cv + 2] * x2 + Bq[3 * j + 2];
            base[j]     = make_float2(kj, kj);   // floats 0,2,4 (pairs)
            base[3 + j] = make_float2(vj, vj);   // floats 6,8,10
        }
    }
    __syncthreads();

    // ---- Two packed query-pairs per thread ----
    // pair j covers n = qb*QBLK + j*2*THREADS + 2*tid + {0,1}
    unsigned long long qx[2], qy[2], qz[2];
    unsigned long long sum[2], ax[2], ay[2], az[2];

    #pragma unroll
    for (int j = 0; j < 2; j++) {
        const int n = qb * QBLK + j * 2 * THREADS + 2 * tid;
        float qc[2][3];
        #pragma unroll
        for (int h = 0; h < 2; h++) {
            const float x0 = xb[(n + h) * 3 + 0];
            const float x1 = xb[(n + h) * 3 + 1];
            const float x2 = xb[(n + h) * 3 + 2];
            qc[h][0] = (W[0]  * x0 + W[1]  * x1 + W[2]  * x2 + Bq[0]) * QFOLD;
            qc[h][1] = (W[9]  * x0 + W[10] * x1 + W[11] * x2 + Bq[3]) * QFOLD;
            qc[h][2] = (W[18] * x0 + W[19] * x1 + W[20] * x2 + Bq[6]) * QFOLD;
        }
        qx[j] = pack2(qc[0][0], qc[1][0]);
        qy[j] = pack2(qc[0][1], qc[1][1]);
        qz[j] = pack2(qc[0][2], qc[1][2]);
        sum[j] = 0ULL; ax[j] = 0ULL; ay[j] = 0ULL; az[j] = 0ULL;
    }

    const ulonglong2* kv2 = reinterpret_cast<const ulonglong2*>(skv);

    #pragma unroll 4
    for (int m = 0; m < MCHUNK; m++) {
        ulonglong2 A  = kv2[3 * m + 0];   // .x={kx,kx} .y={ky,ky}
        ulonglong2 Bv = kv2[3 * m + 1];   // .x={kz,kz} .y={vx,vx}
        ulonglong2 C  = kv2[3 * m + 2];   // .x={vy,vy} .y={vz,vz}

        #pragma unroll
        for (int j = 0; j < 2; j++) {
            // s = {score(q_a, m), score(q_b, m)} in log2 domain
            unsigned long long s2 = fma2(qz[j], Bv.x, fma2(qy[j], A.y, mul2(qx[j], A.x)));
            unsigned long long e2 = ex2_pair(s2);

            sum[j] = add2(sum[j], e2);
            ax[j]  = fma2(e2, Bv.y, ax[j]);
            ay[j]  = fma2(e2, C.x,  ay[j]);
            az[j]  = fma2(e2, C.y,  az[j]);
        }
    }

    // ---- Unpack query-pair accumulators; emit partials per query ----
    const size_t pbase = (size_t)(b * NCH + ch) * NN;
    #pragma unroll
    for (int j = 0; j < 2; j++) {
        const int n = qb * QBLK + j * 2 * THREADS + 2 * tid;
        float sa, sb, xa, xb2, ya, yb, za, zb;
        unpack2(sum[j], sa, sb); unpack2(ax[j], xa, xb2);
        unpack2(ay[j], ya, yb);  unpack2(az[j], za, zb);
        float4 ra; ra.x = sa; ra.y = xa; ra.z = ya; ra.w = za;
        float4 rb; rb.x = sb; rb.y = xb2; rb.z = yb; rb.w = zb;
        g_partial[pbase + n]     = ra;
        g_partial[pbase + n + 1] = rb;
    }
}

// ---------------------------------------------------------------------------
// Kernel 2: reduce the NCH=16 chunk partials, normalize, add residual.
// 2 threads per output (8 chunks each, MLP=8), shfl_xor combine.
// ---------------------------------------------------------------------------
__global__ __launch_bounds__(128) void attn_final_kernel(
    const float* __restrict__ X, float* __restrict__ O)
{
    const int gid  = blockIdx.x * 128 + threadIdx.x;  // 0 .. 2*B*N-1
    const int idx  = gid >> 1;                         // output index
    const int half = gid & 1;                          // chunk half
    const int b = idx >> 13;
    const int n = idx & (NN - 1);

    const float4* pb = g_partial + (size_t)(b * NCH + half * 8) * NN + n;

    float s = 0.f, a0 = 0.f, a1 = 0.f, a2 = 0.f;
    #pragma unroll
    for (int c = 0; c < 8; c++) {
        float4 r = pb[(size_t)c * NN];
        s  += r.x;
        a0 += r.y;
        a1 += r.z;
        a2 += r.w;
    }
    s  += __shfl_xor_sync(0xFFFFFFFFu, s, 1);
    a0 += __shfl_xor_sync(0xFFFFFFFFu, a0, 1);
    a1 += __shfl_xor_sync(0xFFFFFFFFu, a1, 1);
    a2 += __shfl_xor_sync(0xFFFFFFFFu, a2, 1);

    if (half == 0) {
        const float inv = __fdividef(1.0f, s);
        const size_t o = (size_t)idx * 3;
        O[o + 0] = a0 * inv + X[o + 0];
        O[o + 1] = a1 * inv + X[o + 1];
        O[o + 2] = a2 * inv + X[o + 2];
    }
}

extern "C" void kernel_launch(void* const* d_in, const int* in_sizes, int n_in,
                              void* d_out, int out_size) {
    const float* X  = (const float*)d_in[0];  // pixel_features (4, 8192, 3)
    const float* W  = (const float*)d_in[1];  // W_qkv (9, 3)
    const float* Bq = (const float*)d_in[2];  // b_qkv (9,)
    float* O = (float*)d_out;

    dim3 grid1(NCH, NQB, NB);   // (16, 16, 4) = 1024 CTAs
    attn_partial_kernel<<<grid1, THREADS>>>(X, W, Bq);

    attn_final_kernel<<<(2 * NB * NN) / 128, 128>>>(X, O);
}

// round 16
// speedup vs baseline: 1.0524x; 1.0524x over previous
#include <cuda_runtime.h>

// Problem constants
#define NB 4
#define NN 8192
#define MCHUNK 512             // m's per chunk (SMEM tile)
#define NCH (NN / MCHUNK)      // 16 m-chunks
#define THREADS 128
#define QPT 4                  // queries per thread (as 2 packed query-pairs)
#define QBLK (THREADS * QPT)   // 512 queries per CTA
#define NQB (NN / QBLK)        // 16 query blocks

// Per-(batch, m-chunk, query) partials: {sum_e, ax, ay, az}. 4*16*8192*16B = 8MB (L2-resident).
__device__ float4 g_partial[NB * NCH * NN];

// ---------- f32x2 helpers (sm_103a packed fp32) ----------
__device__ __forceinline__ unsigned long long pack2(float lo, float hi) {
    unsigned long long r;
    asm("mov.b64 %0, {%1, %2};" : "=l"(r) : "f"(lo), "f"(hi));
    return r;
}
__device__ __forceinline__ void unpack2(unsigned long long v, float& lo, float& hi) {
    asm("mov.b64 {%0, %1}, %2;" : "=f"(lo), "=f"(hi) : "l"(v));
}
__device__ __forceinline__ unsigned long long fma2(unsigned long long a, unsigned long long b,
                                                   unsigned long long c) {
    unsigned long long r;
    asm("fma.rn.f32x2 %0, %1, %2, %3;" : "=l"(r) : "l"(a), "l"(b), "l"(c));
    return r;
}
__device__ __forceinline__ unsigned long long mul2(unsigned long long a, unsigned long long b) {
    unsigned long long r;
    asm("mul.rn.f32x2 %0, %1, %2;" : "=l"(r) : "l"(a), "l"(b));
    return r;
}
__device__ __forceinline__ unsigned long long add2(unsigned long long a, unsigned long long b) {
    unsigned long long r;
    asm("add.rn.f32x2 %0, %1, %2;" : "=l"(r) : "l"(a), "l"(b));
    return r;
}
// ex2 on both halves of a packed f32x2 (ptxas coalesces the movs when
// register allocation permits).
__device__ __forceinline__ unsigned long long ex2_pair(unsigned long long s2) {
    unsigned long long r;
    asm("{\n\t"
        ".reg .f32 lo, hi;\n\t"
        "mov.b64 {lo, hi}, %1;\n\t"
        "ex2.approx.ftz.f32 lo, lo;\n\t"
        "ex2.approx.ftz.f32 hi, hi;\n\t"
        "mov.b64 %0, {lo, hi};\n\t"
        "}" : "=l"(r) : "l"(s2));
    return r;
}

// log2(e) / sqrt(3): folds the attention scale and the exp->ex2 conversion into q.
#define QFOLD 0.8329433338549414f

// ---------------------------------------------------------------------------
// Kernel 1: per (batch, m-chunk) partial softmax numerators.
// Packing axis = QUERY pairs: smem holds k/v components pre-duplicated
// ({kx,kx},{ky,ky},...), each thread carries 2 packed query-pairs
// ({q_a,q_b} per component). This halves q-pack + accumulator registers
// (~96 -> ~70) so 6 CTAs (24 warps) fit per SM for latency absorption.
// Warp smem reads are same-address broadcasts (conflict-free).
// ---------------------------------------------------------------------------
__global__ __launch_bounds__(THREADS, 6) void attn_partial_kernel(
    const float* __restrict__ X,   // (B, N, 3)
    const float* __restrict__ W,   // (9, 3) row-major
    const float* __restrict__ Bq)  // (9,)
{
    // Per m: 12 floats [kx kx ky ky | kz kz vx vx | vy vy vz vz] = 48B,
    // 16B-aligned triplets -> 3 x LDS.128, each half a ready f32x2 operand.
    __shared__ __align__(16) float skv[MCHUNK * 12];   // 24 KB

    const int ch  = blockIdx.x;   // m-chunk
    const int qb  = blockIdx.y;   // query block
    const int b   = blockIdx.z;   // batch
    const int tid = threadIdx.x;

    const float* xb = X + (size_t)b * NN * 3;

    // ---- Fill SMEM: project k,v for this m-chunk (4 m's per thread) ----
    #pragma unroll
    for (int i = 0; i < MCHUNK; i += THREADS) {
        const int ml = i + tid;
        const int m  = ch * MCHUNK + ml;
        const float x0 = xb[m * 3 + 0];
        const float x1 = xb[m * 3 + 1];
        const float x2 = xb[m * 3 + 2];
        float2* base = reinterpret_cast<float2*>(skv + 12 * ml);
        #pragma unroll
        for (int j = 0; j < 3; j++) {
            // k_j = qkv column 3j+1, v_j = column 3j+2
            const int ck = (3 * j + 1) * 3;
            const int cv = (3 * j + 2) * 3;
            float kj = W[ck + 0] * x0 + W[ck + 1] * x1 + W[ck + 2] * x2 + Bq[3 * j + 1];
            float vj = W[cv + 0] * x0 + W[cv + 1] * x1 + W[cv + 2] * x2 + Bq[3 * j + 2];
            base[j]     = make_float2(kj, kj);   // floats 0,2,4 (pairs)
            base[3 + j] = make_float2(vj, vj);   // floats 6,8,10
        }
    }
    __syncthreads();

    // ---- Two packed query-pairs per thread ----
    // pair j covers n = qb*QBLK + j*2*THREADS + 2*tid + {0,1}
    unsigned long long qx[2], qy[2], qz[2];
    unsigned long long sum[2], ax[2], ay[2], az[2];

    #pragma unroll
    for (int j = 0; j < 2; j++) {
        const int n = qb * QBLK + j * 2 * THREADS + 2 * tid;
        float qc[2][3];
        #pragma unroll
        for (int h = 0; h < 2; h++) {
            const float x0 = xb[(n + h) * 3 + 0];
            const float x1 = xb[(n + h) * 3 + 1];
            const float x2 = xb[(n + h) * 3 + 2];
            qc[h][0] = (W[0]  * x0 + W[1]  * x1 + W[2]  * x2 + Bq[0]) * QFOLD;
            qc[h][1] = (W[9]  * x0 + W[10] * x1 + W[11] * x2 + Bq[3]) * QFOLD;
            qc[h][2] = (W[18] * x0 + W[19] * x1 + W[20] * x2 + Bq[6]) * QFOLD;
        }
        qx[j] = pack2(qc[0][0], qc[1][0]);
        qy[j] = pack2(qc[0][1], qc[1][1]);
        qz[j] = pack2(qc[0][2], qc[1][2]);
        sum[j] = 0ULL; ax[j] = 0ULL; ay[j] = 0ULL; az[j] = 0ULL;
    }

    const ulonglong2* kv2 = reinterpret_cast<const ulonglong2*>(skv);

    #pragma unroll 4
    for (int m = 0; m < MCHUNK; m++) {
        ulonglong2 A  = kv2[3 * m + 0];   // .x={kx,kx} .y={ky,ky}
        ulonglong2 Bv = kv2[3 * m + 1];   // .x={kz,kz} .y={vx,vx}
        ulonglong2 C  = kv2[3 * m + 2];   // .x={vy,vy} .y={vz,vz}

        #pragma unroll
        for (int j = 0; j < 2; j++) {
            // s = {score(q_a, m), score(q_b, m)} in log2 domain
            unsigned long long s2 = fma2(qz[j], Bv.x, fma2(qy[j], A.y, mul2(qx[j], A.x)));
            unsigned long long e2 = ex2_pair(s2);

            sum[j] = add2(sum[j], e2);
            ax[j]  = fma2(e2, Bv.y, ax[j]);
            ay[j]  = fma2(e2, C.x,  ay[j]);
            az[j]  = fma2(e2, C.y,  az[j]);
        }
    }

    // ---- Unpack query-pair accumulators; emit partials per query ----
    const size_t pbase = (size_t)(b * NCH + ch) * NN;
    #pragma unroll
    for (int j = 0; j < 2; j++) {
        const int n = qb * QBLK + j * 2 * THREADS + 2 * tid;
        float sa, sb, xa, xb2, ya, yb, za, zb;
        unpack2(sum[j], sa, sb); unpack2(ax[j], xa, xb2);
        unpack2(ay[j], ya, yb);  unpack2(az[j], za, zb);
        float4 ra; ra.x = sa; ra.y = xa; ra.z = ya; ra.w = za;
        float4 rb; rb.x = sb; rb.y = xb2; rb.z = yb; rb.w = zb;
        g_partial[pbase + n]     = ra;
        g_partial[pbase + n + 1] = rb;
    }
}

// ---------------------------------------------------------------------------
// Kernel 2: reduce the NCH=16 chunk partials, normalize, add residual.
// 2 threads per output (8 chunks each, MLP=8), shfl_xor combine.
// ---------------------------------------------------------------------------
__global__ __launch_bounds__(128) void attn_final_kernel(
    const float* __restrict__ X, float* __restrict__ O)
{
    const int gid  = blockIdx.x * 128 + threadIdx.x;  // 0 .. 2*B*N-1
    const int idx  = gid >> 1;                         // output index
    const int half = gid & 1;                          // chunk half
    const int b = idx >> 13;
    const int n = idx & (NN - 1);

    const float4* pb = g_partial + (size_t)(b * NCH + half * 8) * NN + n;

    float s = 0.f, a0 = 0.f, a1 = 0.f, a2 = 0.f;
    #pragma unroll
    for (int c = 0; c < 8; c++) {
        float4 r = pb[(size_t)c * NN];
        s  += r.x;
        a0 += r.y;
        a1 += r.z;
        a2 += r.w;
    }
    s  += __shfl_xor_sync(0xFFFFFFFFu, s, 1);
    a0 += __shfl_xor_sync(0xFFFFFFFFu, a0, 1);
    a1 += __shfl_xor_sync(0xFFFFFFFFu, a1, 1);
    a2 += __shfl_xor_sync(0xFFFFFFFFu, a2, 1);

    if (half == 0) {
        const float inv = __fdividef(1.0f, s);
        const size_t o = (size_t)idx * 3;
        O[o + 0] = a0 * inv + X[o + 0];
        O[o + 1] = a1 * inv + X[o + 1];
        O[o + 2] = a2 * inv + X[o + 2];
    }
}

extern "C" void kernel_launch(void* const* d_in, const int* in_sizes, int n_in,
                              void* d_out, int out_size) {
    const float* X  = (const float*)d_in[0];  // pixel_features (4, 8192, 3)
    const float* W  = (const float*)d_in[1];  // W_qkv (9, 3)
    const float* Bq = (const float*)d_in[2];  // b_qkv (9,)
    float* O = (float*)d_out;

    dim3 grid1(NCH, NQB, NB);   // (16, 16, 4) = 1024 CTAs
    attn_partial_kernel<<<grid1, THREADS>>>(X, W, Bq);

    attn_final_kernel<<<(2 * NB * NN) / 128, 128>>>(X, O);
}